// round 10
// baseline (speedup 1.0000x reference)
#include <cuda_runtime.h>
#include <cuda_bf16.h>
#include <mma.h>
#include <cstdint>

using namespace nvcuda;

// ---------------------------------------------------------------------------
// GCN 2-layer forward. N=50000, d 128->128->64, E=800000 (+ implicit self loops)
// edge_index int32. tf32 tensor-core GEMMs (cp.async pipeline); atomic-free
// CSR gather aggregation (fp32, edge-loop unrolled x4 for MLP).
// CSR build overlapped with GEMM1 via stream fork.
// ---------------------------------------------------------------------------

#define N_NODES 50000
#define M_PAD   50048
#define D_IN    128
#define D_HID   128
#define D_OUT   64
#define E_MAX   800000
#define NBLK    ((N_NODES + 255) / 256)   // 196

__device__ __align__(16) float g_dinv[N_NODES];
__device__ int   g_count[N_NODES];
__device__ int   g_rowptr[N_NODES + 1];
__device__ int   g_cursor[N_NODES];
__device__ int   g_bsum[NBLK];
__device__ __align__(16) int2  g_csr[E_MAX];       // {src, weight bits}
__device__ __align__(16) float g_H1[(size_t)M_PAD * D_HID];
__device__ __align__(16) float g_OUT1[(size_t)M_PAD * D_HID];
__device__ __align__(16) float g_H2[(size_t)M_PAD * D_OUT];

// ---------------------------------------------------------------------------
// cp.async helpers
// ---------------------------------------------------------------------------
__device__ __forceinline__ void cp_async16(void* smem, const void* gmem, int srcbytes) {
    uint32_t s = (uint32_t)__cvta_generic_to_shared(smem);
    asm volatile("cp.async.cg.shared.global [%0], [%1], 16, %2;\n"
                 :: "r"(s), "l"(gmem), "r"(srcbytes));
}
__device__ __forceinline__ void cp_commit() {
    asm volatile("cp.async.commit_group;\n");
}
template <int N>
__device__ __forceinline__ void cp_wait() {
    asm volatile("cp.async.wait_group %0;\n" :: "n"(N));
}

// ---------------------------------------------------------------------------
// degree + dinv + CSR build (ILP-4 hist/bin)
// ---------------------------------------------------------------------------
__global__ void k_deg_hist4(const int4* __restrict__ dst4, int E4, int E) {
    int t = blockIdx.x * blockDim.x + threadIdx.x;
    if (t < E4) {
        int4 d = __ldg(&dst4[t]);
        atomicAdd(&g_count[d.x], 1);
        atomicAdd(&g_count[d.y], 1);
        atomicAdd(&g_count[d.z], 1);
        atomicAdd(&g_count[d.w], 1);
    }
    if (t == 0) {
        const int* d = (const int*)dst4;
        for (int e = E4 * 4; e < E; e++) atomicAdd(&g_count[d[e]], 1);
    }
}

__device__ __forceinline__ int warp_iscan(int x, int lane) {
    #pragma unroll
    for (int o = 1; o < 32; o <<= 1) {
        int y = __shfl_up_sync(0xffffffffu, x, o);
        if (lane >= o) x += y;
    }
    return x;
}

__global__ void k_scan1(int n) {
    int i = blockIdx.x * 256 + threadIdx.x;
    int lane = threadIdx.x & 31, w = threadIdx.x >> 5;
    int v = (i < n) ? g_count[i] : 0;
    if (i < n) g_dinv[i] = rsqrtf(1.0f + (float)v);   // +1 self loop
    int x = warp_iscan(v, lane);
    __shared__ int wsum[8];
    if (lane == 31) wsum[w] = x;
    __syncthreads();
    if (w == 0) {
        int s = (lane < 8) ? wsum[lane] : 0;
        #pragma unroll
        for (int o = 1; o < 8; o <<= 1) {
            int y = __shfl_up_sync(0xffffffffu, s, o);
            if (lane >= o) s += y;
        }
        if (lane < 8) wsum[lane] = s;
    }
    __syncthreads();
    int incl = x + ((w > 0) ? wsum[w - 1] : 0);
    if (i < n) g_rowptr[i] = incl - v;
    if (threadIdx.x == 255) g_bsum[blockIdx.x] = incl;
}

__global__ void k_scan2apply(int n, int E) {
    int t = threadIdx.x;
    int lane = t & 31, w = t >> 5;
    int v = (t < NBLK) ? g_bsum[t] : 0;
    int x = warp_iscan(v, lane);
    __shared__ int wsum[8];
    __shared__ int sb[256];
    if (lane == 31) wsum[w] = x;
    __syncthreads();
    if (w == 0) {
        int s = (lane < 8) ? wsum[lane] : 0;
        #pragma unroll
        for (int o = 1; o < 8; o <<= 1) {
            int y = __shfl_up_sync(0xffffffffu, s, o);
            if (lane >= o) s += y;
        }
        if (lane < 8) wsum[lane] = s;
    }
    __syncthreads();
    sb[t] = x + ((w > 0) ? wsum[w - 1] : 0) - v;
    __syncthreads();

    int i = blockIdx.x * 256 + t;
    if (i < n) {
        int r = g_rowptr[i] + sb[blockIdx.x];
        g_rowptr[i] = r;
        g_cursor[i] = r;
    }
    if (i == n) g_rowptr[n] = E;
}

__global__ void k_bin4(const int4* __restrict__ src4,
                       const int4* __restrict__ dst4, int E4, int E) {
    int t = blockIdx.x * blockDim.x + threadIdx.x;
    if (t < E4) {
        int4 s = __ldg(&src4[t]);
        int4 d = __ldg(&dst4[t]);
        int p0 = atomicAdd(&g_cursor[d.x], 1);
        int p1 = atomicAdd(&g_cursor[d.y], 1);
        int p2 = atomicAdd(&g_cursor[d.z], 1);
        int p3 = atomicAdd(&g_cursor[d.w], 1);
        g_csr[p0] = make_int2(s.x, __float_as_int(g_dinv[s.x]));
        g_csr[p1] = make_int2(s.y, __float_as_int(g_dinv[s.y]));
        g_csr[p2] = make_int2(s.z, __float_as_int(g_dinv[s.z]));
        g_csr[p3] = make_int2(s.w, __float_as_int(g_dinv[s.w]));
    }
    if (t == 0) {
        const int* s = (const int*)src4;
        const int* d = (const int*)dst4;
        for (int e = E4 * 4; e < E; e++) {
            int pos = atomicAdd(&g_cursor[d[e]], 1);
            g_csr[pos] = make_int2(s[e], __float_as_int(g_dinv[s[e]]));
        }
    }
}

// ---------------------------------------------------------------------------
// tf32 tensor-core GEMM with cp.async 2-stage pipeline. 128x64 tile, 8 warps.
// ---------------------------------------------------------------------------
#define AS_LD 36
#define BS_LD 68
#define GEMM_SMEM (2 * (128 * AS_LD + 32 * BS_LD) * 4)

__global__ void __launch_bounds__(256)
k_gemm_tc(const float* __restrict__ A,
          const float* __restrict__ W,
          float* __restrict__ C,
          int M, int K, int N) {
    extern __shared__ __align__(16) float smem[];
    float (*As)[128][AS_LD] = reinterpret_cast<float (*)[128][AS_LD]>(smem);
    float (*Bs)[32][BS_LD]  = reinterpret_cast<float (*)[32][BS_LD]>(smem + 2 * 128 * AS_LD);

    const int tid = threadIdx.x;
    const int warp = tid >> 5;
    const int warp_m = warp & 3;
    const int warp_n = warp >> 2;
    const int row_base = blockIdx.y * 128;
    const int col_base = blockIdx.x * 64;

    const int a_r = tid >> 3;
    const int a_kv = tid & 7;
    const int b_kr = tid >> 4;
    const int b_cv = tid & 15;

    const int nchunks = K >> 5;

    auto load_chunk = [&](int c, int buf) {
        int k0 = c << 5;
        #pragma unroll
        for (int p = 0; p < 4; p++) {
            int r = p * 32 + a_r;
            int grow = row_base + r;
            int ok = (grow < M) ? 16 : 0;
            int ga = (grow < M) ? grow : (M - 1);
            cp_async16(&As[buf][r][a_kv * 4],
                       &A[(size_t)ga * K + k0 + a_kv * 4], ok);
        }
        #pragma unroll
        for (int p = 0; p < 2; p++) {
            int kr = p * 16 + b_kr;
            cp_async16(&Bs[buf][kr][b_cv * 4],
                       &W[(size_t)(k0 + kr) * N + col_base + b_cv * 4], 16);
        }
    };

    wmma::fragment<wmma::accumulator, 16, 16, 8, float> acc[2][2];
    #pragma unroll
    for (int i = 0; i < 2; i++)
        #pragma unroll
        for (int j = 0; j < 2; j++)
            wmma::fill_fragment(acc[i][j], 0.0f);

    load_chunk(0, 0);
    cp_commit();

    for (int c = 0; c < nchunks; c++) {
        if (c + 1 < nchunks) {
            load_chunk(c + 1, (c + 1) & 1);
            cp_commit();
            cp_wait<1>();
        } else {
            cp_wait<0>();
        }
        __syncthreads();

        int buf = c & 1;
        #pragma unroll
        for (int ks = 0; ks < 4; ks++) {
            wmma::fragment<wmma::matrix_a, 16, 16, 8, wmma::precision::tf32,
                           wmma::row_major> fa[2];
            wmma::fragment<wmma::matrix_b, 16, 16, 8, wmma::precision::tf32,
                           wmma::row_major> fb[2];
            #pragma unroll
            for (int i = 0; i < 2; i++) {
                wmma::load_matrix_sync(fa[i], &As[buf][warp_m * 32 + i * 16][ks * 8], AS_LD);
                #pragma unroll
                for (int t = 0; t < fa[i].num_elements; t++)
                    fa[i].x[t] = wmma::__float_to_tf32(fa[i].x[t]);
            }
            #pragma unroll
            for (int j = 0; j < 2; j++) {
                wmma::load_matrix_sync(fb[j], &Bs[buf][ks * 8][warp_n * 32 + j * 16], BS_LD);
                #pragma unroll
                for (int t = 0; t < fb[j].num_elements; t++)
                    fb[j].x[t] = wmma::__float_to_tf32(fb[j].x[t]);
            }
            #pragma unroll
            for (int i = 0; i < 2; i++)
                #pragma unroll
                for (int j = 0; j < 2; j++)
                    wmma::mma_sync(acc[i][j], fa[i], fb[j], acc[i][j]);
        }
        __syncthreads();
    }

    #pragma unroll
    for (int i = 0; i < 2; i++)
        #pragma unroll
        for (int j = 0; j < 2; j++) {
            int r = row_base + warp_m * 32 + i * 16;
            int c2 = col_base + warp_n * 32 + j * 16;
            wmma::store_matrix_sync(&C[(size_t)r * N + c2], acc[i][j], N,
                                    wmma::mem_row_major);
        }
}

// ---------------------------------------------------------------------------
// CSR gather aggregation, fp32, edge loop unrolled x4 with 4 accumulators
// (4 independent L2 row fetches in flight). TPN lanes per node, float4 each.
// ---------------------------------------------------------------------------
__device__ __forceinline__ void f4_fma(float4& a, float4 v, float w) {
    a.x = fmaf(v.x, w, a.x);
    a.y = fmaf(v.y, w, a.y);
    a.z = fmaf(v.z, w, a.z);
    a.w = fmaf(v.w, w, a.w);
}

template <int TPN, bool RELU>
__global__ void k_agg(const float4* __restrict__ H,
                      const float* __restrict__ bias,
                      float4* __restrict__ out, int n) {
    int t = blockIdx.x * blockDim.x + threadIdx.x;
    int node = t / TPN;
    int q = t % TPN;
    if (node >= n) return;

    float dv = g_dinv[node];
    int beg = __ldg(&g_rowptr[node]);
    int end = __ldg(&g_rowptr[node + 1]);

    float4 h = __ldg(&H[(size_t)node * TPN + q]);
    float self = dv * dv;
    float4 a0 = make_float4(h.x * self, h.y * self, h.z * self, h.w * self);
    float4 a1 = make_float4(0.f, 0.f, 0.f, 0.f);
    float4 a2 = make_float4(0.f, 0.f, 0.f, 0.f);
    float4 a3 = make_float4(0.f, 0.f, 0.f, 0.f);

    int e = beg;
    for (; e + 3 < end; e += 4) {
        int2 m0 = __ldg(&g_csr[e]);
        int2 m1 = __ldg(&g_csr[e + 1]);
        int2 m2 = __ldg(&g_csr[e + 2]);
        int2 m3 = __ldg(&g_csr[e + 3]);
        float4 v0 = __ldg(&H[(size_t)m0.x * TPN + q]);
        float4 v1 = __ldg(&H[(size_t)m1.x * TPN + q]);
        float4 v2 = __ldg(&H[(size_t)m2.x * TPN + q]);
        float4 v3 = __ldg(&H[(size_t)m3.x * TPN + q]);
        f4_fma(a0, v0, __int_as_float(m0.y) * dv);
        f4_fma(a1, v1, __int_as_float(m1.y) * dv);
        f4_fma(a2, v2, __int_as_float(m2.y) * dv);
        f4_fma(a3, v3, __int_as_float(m3.y) * dv);
    }
    for (; e < end; e++) {
        int2 m = __ldg(&g_csr[e]);
        float4 v = __ldg(&H[(size_t)m.x * TPN + q]);
        f4_fma(a0, v, __int_as_float(m.y) * dv);
    }

    float4 acc = make_float4(a0.x + a1.x + a2.x + a3.x,
                             a0.y + a1.y + a2.y + a3.y,
                             a0.z + a1.z + a2.z + a3.z,
                             a0.w + a1.w + a2.w + a3.w);

    float4 bb = *reinterpret_cast<const float4*>(&bias[q * 4]);
    acc.x += bb.x; acc.y += bb.y; acc.z += bb.z; acc.w += bb.w;
    if (RELU) {
        acc.x = fmaxf(acc.x, 0.f); acc.y = fmaxf(acc.y, 0.f);
        acc.z = fmaxf(acc.z, 0.f); acc.w = fmaxf(acc.w, 0.f);
    }
    out[(size_t)node * TPN + q] = acc;
}

// ---------------------------------------------------------------------------
// launch: CSR build on capture stream, GEMM1 forked onto side stream.
// ---------------------------------------------------------------------------
extern "C" void kernel_launch(void* const* d_in, const int* in_sizes, int n_in,
                              void* d_out, int out_size) {
    const float* x   = (const float*)d_in[0];
    const int*   ei  = (const int*)d_in[1];    // int32 (JAX x64 disabled)
    const float* W1  = (const float*)d_in[2];
    const float* b1  = (const float*)d_in[3];
    const float* W2  = (const float*)d_in[4];
    const float* b2  = (const float*)d_in[5];
    float*       out = (float*)d_out;

    const int n = in_sizes[0] / D_IN;       // 50000
    const int E = in_sizes[1] / 2;          // 800000
    const int* srcs = ei;
    const int* dsts = ei + E;
    const int E4 = E >> 2;

    float* H1 = nullptr; float* OUT1 = nullptr; float* H2 = nullptr;
    int* cnt = nullptr;
    cudaGetSymbolAddress((void**)&H1,   g_H1);
    cudaGetSymbolAddress((void**)&OUT1, g_OUT1);
    cudaGetSymbolAddress((void**)&H2,   g_H2);
    cudaGetSymbolAddress((void**)&cnt,  g_count);

    static cudaStream_t s1 = nullptr;
    static cudaEvent_t  evFork = nullptr, evJoin = nullptr;
    if (!s1) {
        cudaFuncSetAttribute(k_gemm_tc,
                             cudaFuncAttributeMaxDynamicSharedMemorySize, GEMM_SMEM);
        cudaStreamCreateWithFlags(&s1, cudaStreamNonBlocking);
        cudaEventCreateWithFlags(&evFork, cudaEventDisableTiming);
        cudaEventCreateWithFlags(&evJoin, cudaEventDisableTiming);
    }

    const int T = 256;
    const int nb = (n + T - 1) / T;         // 196
    const int mblocks = (n + 127) / 128;    // 391

    // ---- fork: GEMM1 on s1, concurrent with CSR build on stream 0 ----
    cudaEventRecord(evFork, 0);
    cudaStreamWaitEvent(s1, evFork, 0);
    {
        dim3 grid(D_HID / 64, mblocks);
        k_gemm_tc<<<grid, 256, GEMM_SMEM, s1>>>(x, W1, H1, n, D_IN, D_HID);
    }
    cudaEventRecord(evJoin, s1);

    // ---- CSR build on capture stream ----
    cudaMemsetAsync(cnt, 0, (size_t)n * sizeof(int));
    k_deg_hist4<<<(E4 + T - 1) / T, T>>>((const int4*)dsts, E4, E);
    k_scan1<<<nb, T>>>(n);
    k_scan2apply<<<nb, T>>>(n, E);
    k_bin4<<<(E4 + T - 1) / T, T>>>((const int4*)srcs, (const int4*)dsts, E4, E);

    // ---- join: agg1 needs both H1 and CSR ----
    cudaStreamWaitEvent(0, evJoin, 0);

    // aggregation layer 1: OUT1 = relu(agg(H1) + b1)
    {
        long long work = (long long)n * (D_HID / 4);
        k_agg<D_HID / 4, true><<<(int)((work + T - 1) / T), T>>>(
            (const float4*)H1, b1, (float4*)OUT1, n);
    }

    // GEMM2: H2 = OUT1 @ W2
    {
        dim3 grid(D_OUT / 64, mblocks);
        k_gemm_tc<<<grid, 256, GEMM_SMEM>>>(OUT1, W2, H2, n, D_HID, D_OUT);
    }

    // aggregation layer 2: out = agg(H2) + b2
    {
        long long work = (long long)n * (D_OUT / 4);
        k_agg<D_OUT / 4, false><<<(int)((work + T - 1) / T), T>>>(
            (const float4*)H2, b2, (float4*)out, n);
    }
}

// round 11
// speedup vs baseline: 1.1326x; 1.1326x over previous
#include <cuda_runtime.h>
#include <cuda_bf16.h>
#include <mma.h>
#include <cstdint>

using namespace nvcuda;

// ---------------------------------------------------------------------------
// GCN 2-layer forward. N=50000, d 128->128->64, E=800000 (+ implicit self loops)
// edge_index int32. tf32 tensor-core GEMMs (cp.async pipeline); atomic-free
// CSR gather aggregation. CSR build overlapped with GEMM1 via stream fork.
// R11: single-pass decoupled-lookback scan (epoch-tagged, no reset node),
//      count re-zeroed in-scan (memset node removed). Hot kernels = R6 exact.
// ---------------------------------------------------------------------------

#define N_NODES 50000
#define M_PAD   50048
#define D_IN    128
#define D_HID   128
#define D_OUT   64
#define E_MAX   800000
#define NBLK    ((N_NODES + 255) / 256)   // 196

#define FLAG_AGG 1u
#define FLAG_INC 2u

__device__ __align__(16) float g_dinv[N_NODES];
__device__ int   g_count[N_NODES];            // zero-init; re-zeroed each call
__device__ int   g_rowptr[N_NODES + 1];
__device__ int   g_cursor[N_NODES];
__device__ unsigned long long g_state[NBLK];  // lookback: epoch|flag|value
__device__ unsigned int g_epoch;              // bumped once per call (in hist)
__device__ __align__(16) int2  g_csr[E_MAX];  // {src, weight bits}
__device__ __align__(16) float g_H1[(size_t)M_PAD * D_HID];
__device__ __align__(16) float g_OUT1[(size_t)M_PAD * D_HID];
__device__ __align__(16) float g_H2[(size_t)M_PAD * D_OUT];

// ---------------------------------------------------------------------------
// cp.async helpers
// ---------------------------------------------------------------------------
__device__ __forceinline__ void cp_async16(void* smem, const void* gmem, int srcbytes) {
    uint32_t s = (uint32_t)__cvta_generic_to_shared(smem);
    asm volatile("cp.async.cg.shared.global [%0], [%1], 16, %2;\n"
                 :: "r"(s), "l"(gmem), "r"(srcbytes));
}
__device__ __forceinline__ void cp_commit() {
    asm volatile("cp.async.commit_group;\n");
}
template <int N>
__device__ __forceinline__ void cp_wait() {
    asm volatile("cp.async.wait_group %0;\n" :: "n"(N));
}

// ---------------------------------------------------------------------------
// degree histogram (+ epoch bump for this call)
// ---------------------------------------------------------------------------
__global__ void k_deg_hist(const int* __restrict__ dst, int E) {
    if (blockIdx.x == 0 && threadIdx.x == 0) atomicAdd(&g_epoch, 1u);
    int e = blockIdx.x * blockDim.x + threadIdx.x;
    if (e < E) atomicAdd(&g_count[dst[e]], 1);
}

__device__ __forceinline__ int warp_iscan(int x, int lane) {
    #pragma unroll
    for (int o = 1; o < 32; o <<= 1) {
        int y = __shfl_up_sync(0xffffffffu, x, o);
        if (lane >= o) x += y;
    }
    return x;
}

// ---------------------------------------------------------------------------
// fused single-pass scan: dinv, count re-zero, exclusive prefix via decoupled
// lookback (epoch-tagged state; stale entries from prior replays ignored),
// rowptr + cursor init, rowptr[n]=E.
// ---------------------------------------------------------------------------
__global__ void k_scan_fused(int n, int E) {
    const int b = blockIdx.x;
    const int t = threadIdx.x;
    const int lane = t & 31, w = t >> 5;
    const unsigned int epoch = g_epoch;   // written by prior kernel; stable here

    int i = b * 256 + t;
    int v = (i < n) ? g_count[i] : 0;
    if (i < n) {
        g_dinv[i] = rsqrtf(1.0f + (float)v);   // +1 self loop
        g_count[i] = 0;                        // restore invariant for next call
    }

    int x = warp_iscan(v, lane);
    __shared__ int wsum[8];
    __shared__ int s_prefix;
    if (lane == 31) wsum[w] = x;
    __syncthreads();
    if (w == 0) {
        int s = (lane < 8) ? wsum[lane] : 0;
        #pragma unroll
        for (int o = 1; o < 8; o <<= 1) {
            int y = __shfl_up_sync(0xffffffffu, s, o);
            if (lane >= o) s += y;
        }
        if (lane < 8) wsum[lane] = s;
    }
    __syncthreads();
    int incl = x + ((w > 0) ? wsum[w - 1] : 0);
    int block_total = wsum[7];

    // publish: block 0 -> INC immediately, others -> AGG
    if (t == 0) {
        unsigned int flag = (b == 0) ? FLAG_INC : FLAG_AGG;
        unsigned long long st = ((unsigned long long)epoch << 32)
                              | ((unsigned long long)flag << 30)
                              | (unsigned int)block_total;
        __threadfence();
        atomicExch(&g_state[b], st);
    }

    // lookback (warp 0)
    if (b == 0) {
        if (t == 0) s_prefix = 0;
    } else if (w == 0) {
        int running = 0;
        int j = b - 1;
        while (true) {
            int idx = j - lane;
            unsigned int flag; int val;
            if (idx >= 0) {
                unsigned long long s;
                do {
                    s = *(volatile unsigned long long*)&g_state[idx];
                } while ((unsigned int)(s >> 32) != epoch ||
                         (((s >> 30) & 3u) == 0u));
                flag = (unsigned int)((s >> 30) & 3u);
                val  = (int)(s & 0x3FFFFFFFu);
            } else {
                flag = FLAG_INC; val = 0;   // virtual block -1
            }
            unsigned inc_mask = __ballot_sync(0xffffffffu, flag == FLAG_INC);
            if (inc_mask) {
                int first_inc = __ffs(inc_mask) - 1;   // closest INC predecessor
                int contrib = (lane <= first_inc) ? val : 0;
                #pragma unroll
                for (int o = 16; o; o >>= 1)
                    contrib += __shfl_down_sync(0xffffffffu, contrib, o);
                running += __shfl_sync(0xffffffffu, contrib, 0);
                break;
            } else {
                int contrib = val;
                #pragma unroll
                for (int o = 16; o; o >>= 1)
                    contrib += __shfl_down_sync(0xffffffffu, contrib, o);
                running += __shfl_sync(0xffffffffu, contrib, 0);
                j -= 32;
            }
        }
        if (lane == 0) {
            s_prefix = running;
            unsigned long long st = ((unsigned long long)epoch << 32)
                                  | ((unsigned long long)FLAG_INC << 30)
                                  | (unsigned int)(running + block_total);
            __threadfence();
            atomicExch(&g_state[b], st);
        }
    }
    __syncthreads();

    int prefix = s_prefix;
    if (i < n) {
        int r = (incl - v) + prefix;   // exclusive
        g_rowptr[i] = r;
        g_cursor[i] = r;
    }
    if (i == n) g_rowptr[n] = E;
}

// ---------------------------------------------------------------------------
// bin edges into CSR (scalar, R6-exact)
// ---------------------------------------------------------------------------
__global__ void k_bin(const int* __restrict__ src,
                      const int* __restrict__ dst, int E) {
    int e = blockIdx.x * blockDim.x + threadIdx.x;
    if (e >= E) return;
    int s = src[e], d = dst[e];
    int pos = atomicAdd(&g_cursor[d], 1);
    g_csr[pos] = make_int2(s, __float_as_int(g_dinv[s]));
}

// ---------------------------------------------------------------------------
// tf32 tensor-core GEMM with cp.async 2-stage pipeline. 128x64 tile, 8 warps.
// ---------------------------------------------------------------------------
#define AS_LD 36
#define BS_LD 68
#define GEMM_SMEM (2 * (128 * AS_LD + 32 * BS_LD) * 4)

__global__ void __launch_bounds__(256)
k_gemm_tc(const float* __restrict__ A,
          const float* __restrict__ W,
          float* __restrict__ C,
          int M, int K, int N) {
    extern __shared__ __align__(16) float smem[];
    float (*As)[128][AS_LD] = reinterpret_cast<float (*)[128][AS_LD]>(smem);
    float (*Bs)[32][BS_LD]  = reinterpret_cast<float (*)[32][BS_LD]>(smem + 2 * 128 * AS_LD);

    const int tid = threadIdx.x;
    const int warp = tid >> 5;
    const int warp_m = warp & 3;
    const int warp_n = warp >> 2;
    const int row_base = blockIdx.y * 128;
    const int col_base = blockIdx.x * 64;

    const int a_r = tid >> 3;
    const int a_kv = tid & 7;
    const int b_kr = tid >> 4;
    const int b_cv = tid & 15;

    const int nchunks = K >> 5;

    auto load_chunk = [&](int c, int buf) {
        int k0 = c << 5;
        #pragma unroll
        for (int p = 0; p < 4; p++) {
            int r = p * 32 + a_r;
            int grow = row_base + r;
            int ok = (grow < M) ? 16 : 0;
            int ga = (grow < M) ? grow : (M - 1);
            cp_async16(&As[buf][r][a_kv * 4],
                       &A[(size_t)ga * K + k0 + a_kv * 4], ok);
        }
        #pragma unroll
        for (int p = 0; p < 2; p++) {
            int kr = p * 16 + b_kr;
            cp_async16(&Bs[buf][kr][b_cv * 4],
                       &W[(size_t)(k0 + kr) * N + col_base + b_cv * 4], 16);
        }
    };

    wmma::fragment<wmma::accumulator, 16, 16, 8, float> acc[2][2];
    #pragma unroll
    for (int i = 0; i < 2; i++)
        #pragma unroll
        for (int j = 0; j < 2; j++)
            wmma::fill_fragment(acc[i][j], 0.0f);

    load_chunk(0, 0);
    cp_commit();

    for (int c = 0; c < nchunks; c++) {
        if (c + 1 < nchunks) {
            load_chunk(c + 1, (c + 1) & 1);
            cp_commit();
            cp_wait<1>();
        } else {
            cp_wait<0>();
        }
        __syncthreads();

        int buf = c & 1;
        #pragma unroll
        for (int ks = 0; ks < 4; ks++) {
            wmma::fragment<wmma::matrix_a, 16, 16, 8, wmma::precision::tf32,
                           wmma::row_major> fa[2];
            wmma::fragment<wmma::matrix_b, 16, 16, 8, wmma::precision::tf32,
                           wmma::row_major> fb[2];
            #pragma unroll
            for (int i = 0; i < 2; i++) {
                wmma::load_matrix_sync(fa[i], &As[buf][warp_m * 32 + i * 16][ks * 8], AS_LD);
                #pragma unroll
                for (int t = 0; t < fa[i].num_elements; t++)
                    fa[i].x[t] = wmma::__float_to_tf32(fa[i].x[t]);
            }
            #pragma unroll
            for (int j = 0; j < 2; j++) {
                wmma::load_matrix_sync(fb[j], &Bs[buf][ks * 8][warp_n * 32 + j * 16], BS_LD);
                #pragma unroll
                for (int t = 0; t < fb[j].num_elements; t++)
                    fb[j].x[t] = wmma::__float_to_tf32(fb[j].x[t]);
            }
            #pragma unroll
            for (int i = 0; i < 2; i++)
                #pragma unroll
                for (int j = 0; j < 2; j++)
                    wmma::mma_sync(acc[i][j], fa[i], fb[j], acc[i][j]);
        }
        __syncthreads();
    }

    #pragma unroll
    for (int i = 0; i < 2; i++)
        #pragma unroll
        for (int j = 0; j < 2; j++) {
            int r = row_base + warp_m * 32 + i * 16;
            int c2 = col_base + warp_n * 32 + j * 16;
            wmma::store_matrix_sync(&C[(size_t)r * N + c2], acc[i][j], N,
                                    wmma::mem_row_major);
        }
}

// ---------------------------------------------------------------------------
// CSR gather aggregation (R6-exact). TPN lanes per node, one float4 column.
// ---------------------------------------------------------------------------
template <int TPN, bool RELU>
__global__ void k_agg(const float4* __restrict__ H,
                      const float* __restrict__ bias,
                      float4* __restrict__ out, int n) {
    int t = blockIdx.x * blockDim.x + threadIdx.x;
    int node = t / TPN;
    int q = t % TPN;
    if (node >= n) return;

    float dv = g_dinv[node];
    int beg = __ldg(&g_rowptr[node]);
    int end = __ldg(&g_rowptr[node + 1]);

    float4 h = __ldg(&H[(size_t)node * TPN + q]);
    float self = dv * dv;
    float4 acc = make_float4(h.x * self, h.y * self, h.z * self, h.w * self);

    if (beg < end) {
        int2 cur = __ldg(&g_csr[beg]);
        for (int e = beg; e < end; e++) {
            int2 nxt = (e + 1 < end) ? __ldg(&g_csr[e + 1]) : cur;
            float w = __int_as_float(cur.y) * dv;
            float4 v = __ldg(&H[(size_t)cur.x * TPN + q]);
            acc.x = fmaf(v.x, w, acc.x);
            acc.y = fmaf(v.y, w, acc.y);
            acc.z = fmaf(v.z, w, acc.z);
            acc.w = fmaf(v.w, w, acc.w);
            cur = nxt;
        }
    }
    float4 bb = *reinterpret_cast<const float4*>(&bias[q * 4]);
    acc.x += bb.x; acc.y += bb.y; acc.z += bb.z; acc.w += bb.w;
    if (RELU) {
        acc.x = fmaxf(acc.x, 0.f); acc.y = fmaxf(acc.y, 0.f);
        acc.z = fmaxf(acc.z, 0.f); acc.w = fmaxf(acc.w, 0.f);
    }
    out[(size_t)node * TPN + q] = acc;
}

// ---------------------------------------------------------------------------
// launch: CSR build on capture stream, GEMM1 forked onto side stream.
// ---------------------------------------------------------------------------
extern "C" void kernel_launch(void* const* d_in, const int* in_sizes, int n_in,
                              void* d_out, int out_size) {
    const float* x   = (const float*)d_in[0];
    const int*   ei  = (const int*)d_in[1];    // int32 (JAX x64 disabled)
    const float* W1  = (const float*)d_in[2];
    const float* b1  = (const float*)d_in[3];
    const float* W2  = (const float*)d_in[4];
    const float* b2  = (const float*)d_in[5];
    float*       out = (float*)d_out;

    const int n = in_sizes[0] / D_IN;       // 50000
    const int E = in_sizes[1] / 2;          // 800000
    const int* srcs = ei;
    const int* dsts = ei + E;

    float* H1 = nullptr; float* OUT1 = nullptr; float* H2 = nullptr;
    cudaGetSymbolAddress((void**)&H1,   g_H1);
    cudaGetSymbolAddress((void**)&OUT1, g_OUT1);
    cudaGetSymbolAddress((void**)&H2,   g_H2);

    static cudaStream_t s1 = nullptr;
    static cudaEvent_t  evFork = nullptr, evJoin = nullptr;
    if (!s1) {
        cudaFuncSetAttribute(k_gemm_tc,
                             cudaFuncAttributeMaxDynamicSharedMemorySize, GEMM_SMEM);
        cudaStreamCreateWithFlags(&s1, cudaStreamNonBlocking);
        cudaEventCreateWithFlags(&evFork, cudaEventDisableTiming);
        cudaEventCreateWithFlags(&evJoin, cudaEventDisableTiming);
    }

    const int T = 256;
    const int mblocks = (n + 127) / 128;    // 391

    // ---- fork: GEMM1 on s1, concurrent with CSR build on stream 0 ----
    cudaEventRecord(evFork, 0);
    cudaStreamWaitEvent(s1, evFork, 0);
    {
        dim3 grid(D_HID / 64, mblocks);
        k_gemm_tc<<<grid, 256, GEMM_SMEM, s1>>>(x, W1, H1, n, D_IN, D_HID);
    }
    cudaEventRecord(evJoin, s1);

    // ---- CSR build on capture stream (3 nodes) ----
    k_deg_hist<<<(E + T - 1) / T, T>>>(dsts, E);
    k_scan_fused<<<NBLK, T>>>(n, E);
    k_bin<<<(E + T - 1) / T, T>>>(srcs, dsts, E);

    // ---- join: agg1 needs both H1 and CSR ----
    cudaStreamWaitEvent(0, evJoin, 0);

    // aggregation layer 1: OUT1 = relu(agg(H1) + b1)
    {
        long long work = (long long)n * (D_HID / 4);
        k_agg<D_HID / 4, true><<<(int)((work + T - 1) / T), T>>>(
            (const float4*)H1, b1, (float4*)OUT1, n);
    }

    // GEMM2: H2 = OUT1 @ W2
    {
        dim3 grid(D_OUT / 64, mblocks);
        k_gemm_tc<<<grid, 256, GEMM_SMEM>>>(OUT1, W2, H2, n, D_HID, D_OUT);
    }

    // aggregation layer 2: out = agg(H2) + b2
    {
        long long work = (long long)n * (D_OUT / 4);
        k_agg<D_OUT / 4, false><<<(int)((work + T - 1) / T), T>>>(
            (const float4*)H2, b2, (float4*)out, n);
    }
}

// round 12
// speedup vs baseline: 1.1878x; 1.0487x over previous
#include <cuda_runtime.h>
#include <cuda_fp16.h>
#include <mma.h>
#include <cstdint>

using namespace nvcuda;

// ---------------------------------------------------------------------------
// GCN 2-layer forward. N=50000, d 128->128->64, E=800000 (+ implicit self loops)
// edge_index int32. tf32 tensor-core GEMMs (cp.async pipeline); atomic-free
// CSR gather aggregation. CSR build overlapped with GEMM1 via stream fork.
// R12 = R11 + ISOLATED fp16 experiment on agg1's gather traffic:
//   GEMM1 unchanged (fp32 out) -> k_h1_convert (s1) -> agg1 reads fp16.
// Everything else byte-identical to R11.
// ---------------------------------------------------------------------------

#define N_NODES 50000
#define M_PAD   50048
#define D_IN    128
#define D_HID   128
#define D_OUT   64
#define E_MAX   800000
#define NBLK    ((N_NODES + 255) / 256)   // 196

#define FLAG_AGG 1u
#define FLAG_INC 2u

__device__ __align__(16) float g_dinv[N_NODES];
__device__ int   g_count[N_NODES];            // zero-init; re-zeroed each call
__device__ int   g_rowptr[N_NODES + 1];
__device__ int   g_cursor[N_NODES];
__device__ unsigned long long g_state[NBLK];  // lookback: epoch|flag|value
__device__ unsigned int g_epoch;
__device__ __align__(16) int2   g_csr[E_MAX]; // {src, weight bits}
__device__ __align__(16) float  g_H1[(size_t)M_PAD * D_HID];
__device__ __align__(16) __half g_H1h[(size_t)M_PAD * D_HID];  // fp16 mirror
__device__ __align__(16) float  g_OUT1[(size_t)M_PAD * D_HID];
__device__ __align__(16) float  g_H2[(size_t)M_PAD * D_OUT];

// ---------------------------------------------------------------------------
// cp.async helpers
// ---------------------------------------------------------------------------
__device__ __forceinline__ void cp_async16(void* smem, const void* gmem, int srcbytes) {
    uint32_t s = (uint32_t)__cvta_generic_to_shared(smem);
    asm volatile("cp.async.cg.shared.global [%0], [%1], 16, %2;\n"
                 :: "r"(s), "l"(gmem), "r"(srcbytes));
}
__device__ __forceinline__ void cp_commit() {
    asm volatile("cp.async.commit_group;\n");
}
template <int N>
__device__ __forceinline__ void cp_wait() {
    asm volatile("cp.async.wait_group %0;\n" :: "n"(N));
}

// ---------------------------------------------------------------------------
// degree histogram (+ epoch bump)
// ---------------------------------------------------------------------------
__global__ void k_deg_hist(const int* __restrict__ dst, int E) {
    if (blockIdx.x == 0 && threadIdx.x == 0) atomicAdd(&g_epoch, 1u);
    int e = blockIdx.x * blockDim.x + threadIdx.x;
    if (e < E) atomicAdd(&g_count[dst[e]], 1);
}

__device__ __forceinline__ int warp_iscan(int x, int lane) {
    #pragma unroll
    for (int o = 1; o < 32; o <<= 1) {
        int y = __shfl_up_sync(0xffffffffu, x, o);
        if (lane >= o) x += y;
    }
    return x;
}

// ---------------------------------------------------------------------------
// fused single-pass scan (decoupled lookback, epoch-tagged) — R11 exact
// ---------------------------------------------------------------------------
__global__ void k_scan_fused(int n, int E) {
    const int b = blockIdx.x;
    const int t = threadIdx.x;
    const int lane = t & 31, w = t >> 5;
    const unsigned int epoch = g_epoch;

    int i = b * 256 + t;
    int v = (i < n) ? g_count[i] : 0;
    if (i < n) {
        g_dinv[i] = rsqrtf(1.0f + (float)v);   // +1 self loop
        g_count[i] = 0;
    }

    int x = warp_iscan(v, lane);
    __shared__ int wsum[8];
    __shared__ int s_prefix;
    if (lane == 31) wsum[w] = x;
    __syncthreads();
    if (w == 0) {
        int s = (lane < 8) ? wsum[lane] : 0;
        #pragma unroll
        for (int o = 1; o < 8; o <<= 1) {
            int y = __shfl_up_sync(0xffffffffu, s, o);
            if (lane >= o) s += y;
        }
        if (lane < 8) wsum[lane] = s;
    }
    __syncthreads();
    int incl = x + ((w > 0) ? wsum[w - 1] : 0);
    int block_total = wsum[7];

    if (t == 0) {
        unsigned int flag = (b == 0) ? FLAG_INC : FLAG_AGG;
        unsigned long long st = ((unsigned long long)epoch << 32)
                              | ((unsigned long long)flag << 30)
                              | (unsigned int)block_total;
        __threadfence();
        atomicExch(&g_state[b], st);
    }

    if (b == 0) {
        if (t == 0) s_prefix = 0;
    } else if (w == 0) {
        int running = 0;
        int j = b - 1;
        while (true) {
            int idx = j - lane;
            unsigned int flag; int val;
            if (idx >= 0) {
                unsigned long long s;
                do {
                    s = *(volatile unsigned long long*)&g_state[idx];
                } while ((unsigned int)(s >> 32) != epoch ||
                         (((s >> 30) & 3u) == 0u));
                flag = (unsigned int)((s >> 30) & 3u);
                val  = (int)(s & 0x3FFFFFFFu);
            } else {
                flag = FLAG_INC; val = 0;
            }
            unsigned inc_mask = __ballot_sync(0xffffffffu, flag == FLAG_INC);
            if (inc_mask) {
                int first_inc = __ffs(inc_mask) - 1;
                int contrib = (lane <= first_inc) ? val : 0;
                #pragma unroll
                for (int o = 16; o; o >>= 1)
                    contrib += __shfl_down_sync(0xffffffffu, contrib, o);
                running += __shfl_sync(0xffffffffu, contrib, 0);
                break;
            } else {
                int contrib = val;
                #pragma unroll
                for (int o = 16; o; o >>= 1)
                    contrib += __shfl_down_sync(0xffffffffu, contrib, o);
                running += __shfl_sync(0xffffffffu, contrib, 0);
                j -= 32;
            }
        }
        if (lane == 0) {
            s_prefix = running;
            unsigned long long st = ((unsigned long long)epoch << 32)
                                  | ((unsigned long long)FLAG_INC << 30)
                                  | (unsigned int)(running + block_total);
            __threadfence();
            atomicExch(&g_state[b], st);
        }
    }
    __syncthreads();

    int prefix = s_prefix;
    if (i < n) {
        int r = (incl - v) + prefix;
        g_rowptr[i] = r;
        g_cursor[i] = r;
    }
    if (i == n) g_rowptr[n] = E;
}

// ---------------------------------------------------------------------------
// bin edges into CSR (scalar, R11 exact)
// ---------------------------------------------------------------------------
__global__ void k_bin(const int* __restrict__ src,
                      const int* __restrict__ dst, int E) {
    int e = blockIdx.x * blockDim.x + threadIdx.x;
    if (e >= E) return;
    int s = src[e], d = dst[e];
    int pos = atomicAdd(&g_cursor[d], 1);
    g_csr[pos] = make_int2(s, __float_as_int(g_dinv[s]));
}

// ---------------------------------------------------------------------------
// tf32 tensor-core GEMM with cp.async 2-stage pipeline — R11 exact
// ---------------------------------------------------------------------------
#define AS_LD 36
#define BS_LD 68
#define GEMM_SMEM (2 * (128 * AS_LD + 32 * BS_LD) * 4)

__global__ void __launch_bounds__(256)
k_gemm_tc(const float* __restrict__ A,
          const float* __restrict__ W,
          float* __restrict__ C,
          int M, int K, int N) {
    extern __shared__ __align__(16) float smem[];
    float (*As)[128][AS_LD] = reinterpret_cast<float (*)[128][AS_LD]>(smem);
    float (*Bs)[32][BS_LD]  = reinterpret_cast<float (*)[32][BS_LD]>(smem + 2 * 128 * AS_LD);

    const int tid = threadIdx.x;
    const int warp = tid >> 5;
    const int warp_m = warp & 3;
    const int warp_n = warp >> 2;
    const int row_base = blockIdx.y * 128;
    const int col_base = blockIdx.x * 64;

    const int a_r = tid >> 3;
    const int a_kv = tid & 7;
    const int b_kr = tid >> 4;
    const int b_cv = tid & 15;

    const int nchunks = K >> 5;

    auto load_chunk = [&](int c, int buf) {
        int k0 = c << 5;
        #pragma unroll
        for (int p = 0; p < 4; p++) {
            int r = p * 32 + a_r;
            int grow = row_base + r;
            int ok = (grow < M) ? 16 : 0;
            int ga = (grow < M) ? grow : (M - 1);
            cp_async16(&As[buf][r][a_kv * 4],
                       &A[(size_t)ga * K + k0 + a_kv * 4], ok);
        }
        #pragma unroll
        for (int p = 0; p < 2; p++) {
            int kr = p * 16 + b_kr;
            cp_async16(&Bs[buf][kr][b_cv * 4],
                       &W[(size_t)(k0 + kr) * N + col_base + b_cv * 4], 16);
        }
    };

    wmma::fragment<wmma::accumulator, 16, 16, 8, float> acc[2][2];
    #pragma unroll
    for (int i = 0; i < 2; i++)
        #pragma unroll
        for (int j = 0; j < 2; j++)
            wmma::fill_fragment(acc[i][j], 0.0f);

    load_chunk(0, 0);
    cp_commit();

    for (int c = 0; c < nchunks; c++) {
        if (c + 1 < nchunks) {
            load_chunk(c + 1, (c + 1) & 1);
            cp_commit();
            cp_wait<1>();
        } else {
            cp_wait<0>();
        }
        __syncthreads();

        int buf = c & 1;
        #pragma unroll
        for (int ks = 0; ks < 4; ks++) {
            wmma::fragment<wmma::matrix_a, 16, 16, 8, wmma::precision::tf32,
                           wmma::row_major> fa[2];
            wmma::fragment<wmma::matrix_b, 16, 16, 8, wmma::precision::tf32,
                           wmma::row_major> fb[2];
            #pragma unroll
            for (int i = 0; i < 2; i++) {
                wmma::load_matrix_sync(fa[i], &As[buf][warp_m * 32 + i * 16][ks * 8], AS_LD);
                #pragma unroll
                for (int t = 0; t < fa[i].num_elements; t++)
                    fa[i].x[t] = wmma::__float_to_tf32(fa[i].x[t]);
            }
            #pragma unroll
            for (int j = 0; j < 2; j++) {
                wmma::load_matrix_sync(fb[j], &Bs[buf][ks * 8][warp_n * 32 + j * 16], BS_LD);
                #pragma unroll
                for (int t = 0; t < fb[j].num_elements; t++)
                    fb[j].x[t] = wmma::__float_to_tf32(fb[j].x[t]);
            }
            #pragma unroll
            for (int i = 0; i < 2; i++)
                #pragma unroll
                for (int j = 0; j < 2; j++)
                    wmma::mma_sync(acc[i][j], fa[i], fb[j], acc[i][j]);
        }
        __syncthreads();
    }

    #pragma unroll
    for (int i = 0; i < 2; i++)
        #pragma unroll
        for (int j = 0; j < 2; j++) {
            int r = row_base + warp_m * 32 + i * 16;
            int c2 = col_base + warp_n * 32 + j * 16;
            wmma::store_matrix_sync(&C[(size_t)r * N + c2], acc[i][j], N,
                                    wmma::mem_row_major);
        }
}

// ---------------------------------------------------------------------------
// fp32 -> fp16 convert (runs on s1 right after GEMM1, overlaps CSR build)
// ---------------------------------------------------------------------------
__global__ void k_h1_convert(const float4* __restrict__ in,
                             uint2* __restrict__ out, int total4) {
    int i = blockIdx.x * blockDim.x + threadIdx.x;
    if (i >= total4) return;
    float4 v = __ldg(&in[i]);
    __half2 a = __floats2half2_rn(v.x, v.y);
    __half2 b = __floats2half2_rn(v.z, v.w);
    uint2 o;
    o.x = *reinterpret_cast<const unsigned int*>(&a);
    o.y = *reinterpret_cast<const unsigned int*>(&b);
    out[i] = o;
}

// ---------------------------------------------------------------------------
// agg1 on fp16 H1: TPN=32, lane owns 4 halves (uint2). fp32 accumulate.
//   OUT1 = relu(b1 + H1[i]*dinv^2 + sum_e H1[src]*w*dinv)
// ---------------------------------------------------------------------------
__device__ __forceinline__ void h4_fma(float* acc, uint2 v, float w) {
    __half2 h0 = *reinterpret_cast<const __half2*>(&v.x);
    __half2 h1 = *reinterpret_cast<const __half2*>(&v.y);
    float2 f0 = __half22float2(h0);
    float2 f1 = __half22float2(h1);
    acc[0] = fmaf(f0.x, w, acc[0]);
    acc[1] = fmaf(f0.y, w, acc[1]);
    acc[2] = fmaf(f1.x, w, acc[2]);
    acc[3] = fmaf(f1.y, w, acc[3]);
}

__global__ void k_agg1_h(const uint2* __restrict__ Hh,
                         const float* __restrict__ b1,
                         float4* __restrict__ OUT1, int n) {
    int t = blockIdx.x * blockDim.x + threadIdx.x;
    int node = t >> 5;
    int q = t & 31;
    if (node >= n) return;

    float dv = g_dinv[node];
    int beg = __ldg(&g_rowptr[node]);
    int end = __ldg(&g_rowptr[node + 1]);

    float acc[4] = {};
    uint2 hv = __ldg(&Hh[(size_t)node * 32 + q]);
    h4_fma(acc, hv, dv * dv);

    if (beg < end) {
        int2 cur = __ldg(&g_csr[beg]);
        for (int e = beg; e < end; e++) {
            int2 nxt = (e + 1 < end) ? __ldg(&g_csr[e + 1]) : cur;
            float w = __int_as_float(cur.y) * dv;
            uint2 v = __ldg(&Hh[(size_t)cur.x * 32 + q]);
            h4_fma(acc, v, w);
            cur = nxt;
        }
    }
    float4 bb = *reinterpret_cast<const float4*>(&b1[q * 4]);
    OUT1[(size_t)node * 32 + q] =
        make_float4(fmaxf(acc[0] + bb.x, 0.f), fmaxf(acc[1] + bb.y, 0.f),
                    fmaxf(acc[2] + bb.z, 0.f), fmaxf(acc[3] + bb.w, 0.f));
}

// ---------------------------------------------------------------------------
// agg2 fp32 (R11 exact)
// ---------------------------------------------------------------------------
template <int TPN, bool RELU>
__global__ void k_agg(const float4* __restrict__ H,
                      const float* __restrict__ bias,
                      float4* __restrict__ out, int n) {
    int t = blockIdx.x * blockDim.x + threadIdx.x;
    int node = t / TPN;
    int q = t % TPN;
    if (node >= n) return;

    float dv = g_dinv[node];
    int beg = __ldg(&g_rowptr[node]);
    int end = __ldg(&g_rowptr[node + 1]);

    float4 h = __ldg(&H[(size_t)node * TPN + q]);
    float self = dv * dv;
    float4 acc = make_float4(h.x * self, h.y * self, h.z * self, h.w * self);

    if (beg < end) {
        int2 cur = __ldg(&g_csr[beg]);
        for (int e = beg; e < end; e++) {
            int2 nxt = (e + 1 < end) ? __ldg(&g_csr[e + 1]) : cur;
            float w = __int_as_float(cur.y) * dv;
            float4 v = __ldg(&H[(size_t)cur.x * TPN + q]);
            acc.x = fmaf(v.x, w, acc.x);
            acc.y = fmaf(v.y, w, acc.y);
            acc.z = fmaf(v.z, w, acc.z);
            acc.w = fmaf(v.w, w, acc.w);
            cur = nxt;
        }
    }
    float4 bb = *reinterpret_cast<const float4*>(&bias[q * 4]);
    acc.x += bb.x; acc.y += bb.y; acc.z += bb.z; acc.w += bb.w;
    if (RELU) {
        acc.x = fmaxf(acc.x, 0.f); acc.y = fmaxf(acc.y, 0.f);
        acc.z = fmaxf(acc.z, 0.f); acc.w = fmaxf(acc.w, 0.f);
    }
    out[(size_t)node * TPN + q] = acc;
}

// ---------------------------------------------------------------------------
// launch
// ---------------------------------------------------------------------------
extern "C" void kernel_launch(void* const* d_in, const int* in_sizes, int n_in,
                              void* d_out, int out_size) {
    const float* x   = (const float*)d_in[0];
    const int*   ei  = (const int*)d_in[1];    // int32 (JAX x64 disabled)
    const float* W1  = (const float*)d_in[2];
    const float* b1  = (const float*)d_in[3];
    const float* W2  = (const float*)d_in[4];
    const float* b2  = (const float*)d_in[5];
    float*       out = (float*)d_out;

    const int n = in_sizes[0] / D_IN;       // 50000
    const int E = in_sizes[1] / 2;          // 800000
    const int* srcs = ei;
    const int* dsts = ei + E;

    float* H1 = nullptr; __half* H1h = nullptr;
    float* OUT1 = nullptr; float* H2 = nullptr;
    cudaGetSymbolAddress((void**)&H1,   g_H1);
    cudaGetSymbolAddress((void**)&H1h,  g_H1h);
    cudaGetSymbolAddress((void**)&OUT1, g_OUT1);
    cudaGetSymbolAddress((void**)&H2,   g_H2);

    static cudaStream_t s1 = nullptr;
    static cudaEvent_t  evFork = nullptr, evJoin = nullptr;
    if (!s1) {
        cudaFuncSetAttribute(k_gemm_tc,
                             cudaFuncAttributeMaxDynamicSharedMemorySize, GEMM_SMEM);
        cudaStreamCreateWithFlags(&s1, cudaStreamNonBlocking);
        cudaEventCreateWithFlags(&evFork, cudaEventDisableTiming);
        cudaEventCreateWithFlags(&evJoin, cudaEventDisableTiming);
    }

    const int T = 256;
    const int mblocks = (n + 127) / 128;    // 391

    // ---- fork: GEMM1 + fp16 convert on s1, concurrent with CSR build ----
    cudaEventRecord(evFork, 0);
    cudaStreamWaitEvent(s1, evFork, 0);
    {
        dim3 grid(D_HID / 64, mblocks);
        k_gemm_tc<<<grid, 256, GEMM_SMEM, s1>>>(x, W1, H1, n, D_IN, D_HID);
    }
    {
        int total4 = M_PAD * D_HID / 4;     // 1.6M
        k_h1_convert<<<(total4 + T - 1) / T, T, 0, s1>>>(
            (const float4*)H1, (uint2*)H1h, total4);
    }
    cudaEventRecord(evJoin, s1);

    // ---- CSR build on capture stream (3 nodes) ----
    k_deg_hist<<<(E + T - 1) / T, T>>>(dsts, E);
    k_scan_fused<<<NBLK, T>>>(n, E);
    k_bin<<<(E + T - 1) / T, T>>>(srcs, dsts, E);

    // ---- join ----
    cudaStreamWaitEvent(0, evJoin, 0);

    // agg1 (fp16 gather): OUT1 = relu(agg(H1h) + b1)
    {
        long long work = (long long)n * 32;
        k_agg1_h<<<(int)((work + T - 1) / T), T>>>(
            (const uint2*)H1h, b1, (float4*)OUT1, n);
    }

    // GEMM2: H2 = OUT1 @ W2
    {
        dim3 grid(D_OUT / 64, mblocks);
        k_gemm_tc<<<grid, 256, GEMM_SMEM>>>(OUT1, W2, H2, n, D_HID, D_OUT);
    }

    // agg2: out = agg(H2) + b2
    {
        long long work = (long long)n * (D_OUT / 4);
        k_agg<D_OUT / 4, false><<<(int)((work + T - 1) / T), T>>>(
            (const float4*)H2, b2, (float4*)out, n);
    }
}

// round 13
// speedup vs baseline: 1.1938x; 1.0051x over previous
#include <cuda_runtime.h>
#include <cuda_fp16.h>
#include <mma.h>
#include <cstdint>

using namespace nvcuda;

// ---------------------------------------------------------------------------
// GCN 2-layer forward. N=50000, d 128->128->64, E=800000 (+ implicit self loops)
// edge_index int32. tf32 tensor-core GEMMs (cp.async pipeline, fp32 out);
// atomic-free CSR gather aggregation reading fp16 feature mirrors
// (standalone convert kernels; agg thread counts unchanged).
// CSR build overlapped with GEMM1 via stream fork.
// R13 = R12 + fp16 mirror for H2 feeding agg2.
// ---------------------------------------------------------------------------

#define N_NODES 50000
#define M_PAD   50048
#define D_IN    128
#define D_HID   128
#define D_OUT   64
#define E_MAX   800000
#define NBLK    ((N_NODES + 255) / 256)   // 196

#define FLAG_AGG 1u
#define FLAG_INC 2u

__device__ __align__(16) float g_dinv[N_NODES];
__device__ int   g_count[N_NODES];            // zero-init; re-zeroed each call
__device__ int   g_rowptr[N_NODES + 1];
__device__ int   g_cursor[N_NODES];
__device__ unsigned long long g_state[NBLK];  // lookback: epoch|flag|value
__device__ unsigned int g_epoch;
__device__ __align__(16) int2   g_csr[E_MAX]; // {src, weight bits}
__device__ __align__(16) float  g_H1[(size_t)M_PAD * D_HID];
__device__ __align__(16) __half g_H1h[(size_t)M_PAD * D_HID];  // fp16 mirror
__device__ __align__(16) float  g_OUT1[(size_t)M_PAD * D_HID];
__device__ __align__(16) float  g_H2[(size_t)M_PAD * D_OUT];
__device__ __align__(16) __half g_H2h[(size_t)M_PAD * D_OUT];  // fp16 mirror

// ---------------------------------------------------------------------------
// cp.async helpers
// ---------------------------------------------------------------------------
__device__ __forceinline__ void cp_async16(void* smem, const void* gmem, int srcbytes) {
    uint32_t s = (uint32_t)__cvta_generic_to_shared(smem);
    asm volatile("cp.async.cg.shared.global [%0], [%1], 16, %2;\n"
                 :: "r"(s), "l"(gmem), "r"(srcbytes));
}
__device__ __forceinline__ void cp_commit() {
    asm volatile("cp.async.commit_group;\n");
}
template <int N>
__device__ __forceinline__ void cp_wait() {
    asm volatile("cp.async.wait_group %0;\n" :: "n"(N));
}

// ---------------------------------------------------------------------------
// degree histogram (+ epoch bump)
// ---------------------------------------------------------------------------
__global__ void k_deg_hist(const int* __restrict__ dst, int E) {
    if (blockIdx.x == 0 && threadIdx.x == 0) atomicAdd(&g_epoch, 1u);
    int e = blockIdx.x * blockDim.x + threadIdx.x;
    if (e < E) atomicAdd(&g_count[dst[e]], 1);
}

__device__ __forceinline__ int warp_iscan(int x, int lane) {
    #pragma unroll
    for (int o = 1; o < 32; o <<= 1) {
        int y = __shfl_up_sync(0xffffffffu, x, o);
        if (lane >= o) x += y;
    }
    return x;
}

// ---------------------------------------------------------------------------
// fused single-pass scan (decoupled lookback, epoch-tagged)
// ---------------------------------------------------------------------------
__global__ void k_scan_fused(int n, int E) {
    const int b = blockIdx.x;
    const int t = threadIdx.x;
    const int lane = t & 31, w = t >> 5;
    const unsigned int epoch = g_epoch;

    int i = b * 256 + t;
    int v = (i < n) ? g_count[i] : 0;
    if (i < n) {
        g_dinv[i] = rsqrtf(1.0f + (float)v);   // +1 self loop
        g_count[i] = 0;
    }

    int x = warp_iscan(v, lane);
    __shared__ int wsum[8];
    __shared__ int s_prefix;
    if (lane == 31) wsum[w] = x;
    __syncthreads();
    if (w == 0) {
        int s = (lane < 8) ? wsum[lane] : 0;
        #pragma unroll
        for (int o = 1; o < 8; o <<= 1) {
            int y = __shfl_up_sync(0xffffffffu, s, o);
            if (lane >= o) s += y;
        }
        if (lane < 8) wsum[lane] = s;
    }
    __syncthreads();
    int incl = x + ((w > 0) ? wsum[w - 1] : 0);
    int block_total = wsum[7];

    if (t == 0) {
        unsigned int flag = (b == 0) ? FLAG_INC : FLAG_AGG;
        unsigned long long st = ((unsigned long long)epoch << 32)
                              | ((unsigned long long)flag << 30)
                              | (unsigned int)block_total;
        __threadfence();
        atomicExch(&g_state[b], st);
    }

    if (b == 0) {
        if (t == 0) s_prefix = 0;
    } else if (w == 0) {
        int running = 0;
        int j = b - 1;
        while (true) {
            int idx = j - lane;
            unsigned int flag; int val;
            if (idx >= 0) {
                unsigned long long s;
                do {
                    s = *(volatile unsigned long long*)&g_state[idx];
                } while ((unsigned int)(s >> 32) != epoch ||
                         (((s >> 30) & 3u) == 0u));
                flag = (unsigned int)((s >> 30) & 3u);
                val  = (int)(s & 0x3FFFFFFFu);
            } else {
                flag = FLAG_INC; val = 0;
            }
            unsigned inc_mask = __ballot_sync(0xffffffffu, flag == FLAG_INC);
            if (inc_mask) {
                int first_inc = __ffs(inc_mask) - 1;
                int contrib = (lane <= first_inc) ? val : 0;
                #pragma unroll
                for (int o = 16; o; o >>= 1)
                    contrib += __shfl_down_sync(0xffffffffu, contrib, o);
                running += __shfl_sync(0xffffffffu, contrib, 0);
                break;
            } else {
                int contrib = val;
                #pragma unroll
                for (int o = 16; o; o >>= 1)
                    contrib += __shfl_down_sync(0xffffffffu, contrib, o);
                running += __shfl_sync(0xffffffffu, contrib, 0);
                j -= 32;
            }
        }
        if (lane == 0) {
            s_prefix = running;
            unsigned long long st = ((unsigned long long)epoch << 32)
                                  | ((unsigned long long)FLAG_INC << 30)
                                  | (unsigned int)(running + block_total);
            __threadfence();
            atomicExch(&g_state[b], st);
        }
    }
    __syncthreads();

    int prefix = s_prefix;
    if (i < n) {
        int r = (incl - v) + prefix;
        g_rowptr[i] = r;
        g_cursor[i] = r;
    }
    if (i == n) g_rowptr[n] = E;
}

// ---------------------------------------------------------------------------
// bin edges into CSR
// ---------------------------------------------------------------------------
__global__ void k_bin(const int* __restrict__ src,
                      const int* __restrict__ dst, int E) {
    int e = blockIdx.x * blockDim.x + threadIdx.x;
    if (e >= E) return;
    int s = src[e], d = dst[e];
    int pos = atomicAdd(&g_cursor[d], 1);
    g_csr[pos] = make_int2(s, __float_as_int(g_dinv[s]));
}

// ---------------------------------------------------------------------------
// tf32 tensor-core GEMM with cp.async 2-stage pipeline (fp32 out)
// ---------------------------------------------------------------------------
#define AS_LD 36
#define BS_LD 68
#define GEMM_SMEM (2 * (128 * AS_LD + 32 * BS_LD) * 4)

__global__ void __launch_bounds__(256)
k_gemm_tc(const float* __restrict__ A,
          const float* __restrict__ W,
          float* __restrict__ C,
          int M, int K, int N) {
    extern __shared__ __align__(16) float smem[];
    float (*As)[128][AS_LD] = reinterpret_cast<float (*)[128][AS_LD]>(smem);
    float (*Bs)[32][BS_LD]  = reinterpret_cast<float (*)[32][BS_LD]>(smem + 2 * 128 * AS_LD);

    const int tid = threadIdx.x;
    const int warp = tid >> 5;
    const int warp_m = warp & 3;
    const int warp_n = warp >> 2;
    const int row_base = blockIdx.y * 128;
    const int col_base = blockIdx.x * 64;

    const int a_r = tid >> 3;
    const int a_kv = tid & 7;
    const int b_kr = tid >> 4;
    const int b_cv = tid & 15;

    const int nchunks = K >> 5;

    auto load_chunk = [&](int c, int buf) {
        int k0 = c << 5;
        #pragma unroll
        for (int p = 0; p < 4; p++) {
            int r = p * 32 + a_r;
            int grow = row_base + r;
            int ok = (grow < M) ? 16 : 0;
            int ga = (grow < M) ? grow : (M - 1);
            cp_async16(&As[buf][r][a_kv * 4],
                       &A[(size_t)ga * K + k0 + a_kv * 4], ok);
        }
        #pragma unroll
        for (int p = 0; p < 2; p++) {
            int kr = p * 16 + b_kr;
            cp_async16(&Bs[buf][kr][b_cv * 4],
                       &W[(size_t)(k0 + kr) * N + col_base + b_cv * 4], 16);
        }
    };

    wmma::fragment<wmma::accumulator, 16, 16, 8, float> acc[2][2];
    #pragma unroll
    for (int i = 0; i < 2; i++)
        #pragma unroll
        for (int j = 0; j < 2; j++)
            wmma::fill_fragment(acc[i][j], 0.0f);

    load_chunk(0, 0);
    cp_commit();

    for (int c = 0; c < nchunks; c++) {
        if (c + 1 < nchunks) {
            load_chunk(c + 1, (c + 1) & 1);
            cp_commit();
            cp_wait<1>();
        } else {
            cp_wait<0>();
        }
        __syncthreads();

        int buf = c & 1;
        #pragma unroll
        for (int ks = 0; ks < 4; ks++) {
            wmma::fragment<wmma::matrix_a, 16, 16, 8, wmma::precision::tf32,
                           wmma::row_major> fa[2];
            wmma::fragment<wmma::matrix_b, 16, 16, 8, wmma::precision::tf32,
                           wmma::row_major> fb[2];
            #pragma unroll
            for (int i = 0; i < 2; i++) {
                wmma::load_matrix_sync(fa[i], &As[buf][warp_m * 32 + i * 16][ks * 8], AS_LD);
                #pragma unroll
                for (int t = 0; t < fa[i].num_elements; t++)
                    fa[i].x[t] = wmma::__float_to_tf32(fa[i].x[t]);
            }
            #pragma unroll
            for (int j = 0; j < 2; j++) {
                wmma::load_matrix_sync(fb[j], &Bs[buf][ks * 8][warp_n * 32 + j * 16], BS_LD);
                #pragma unroll
                for (int t = 0; t < fb[j].num_elements; t++)
                    fb[j].x[t] = wmma::__float_to_tf32(fb[j].x[t]);
            }
            #pragma unroll
            for (int i = 0; i < 2; i++)
                #pragma unroll
                for (int j = 0; j < 2; j++)
                    wmma::mma_sync(acc[i][j], fa[i], fb[j], acc[i][j]);
        }
        __syncthreads();
    }

    #pragma unroll
    for (int i = 0; i < 2; i++)
        #pragma unroll
        for (int j = 0; j < 2; j++) {
            int r = row_base + warp_m * 32 + i * 16;
            int c2 = col_base + warp_n * 32 + j * 16;
            wmma::store_matrix_sync(&C[(size_t)r * N + c2], acc[i][j], N,
                                    wmma::mem_row_major);
        }
}

// ---------------------------------------------------------------------------
// fp32 -> fp16 convert (float4 -> 4 halves)
// ---------------------------------------------------------------------------
__global__ void k_convert_h(const float4* __restrict__ in,
                            uint2* __restrict__ out, int total4) {
    int i = blockIdx.x * blockDim.x + threadIdx.x;
    if (i >= total4) return;
    float4 v = __ldg(&in[i]);
    __half2 a = __floats2half2_rn(v.x, v.y);
    __half2 b = __floats2half2_rn(v.z, v.w);
    uint2 o;
    o.x = *reinterpret_cast<const unsigned int*>(&a);
    o.y = *reinterpret_cast<const unsigned int*>(&b);
    out[i] = o;
}

// ---------------------------------------------------------------------------
// fp16 gather aggregation: TPN lanes per node, lane owns 4 halves (uint2).
// fp32 accumulate. Template handles both layers.
// ---------------------------------------------------------------------------
__device__ __forceinline__ void h4_fma(float* acc, uint2 v, float w) {
    __half2 h0 = *reinterpret_cast<const __half2*>(&v.x);
    __half2 h1 = *reinterpret_cast<const __half2*>(&v.y);
    float2 f0 = __half22float2(h0);
    float2 f1 = __half22float2(h1);
    acc[0] = fmaf(f0.x, w, acc[0]);
    acc[1] = fmaf(f0.y, w, acc[1]);
    acc[2] = fmaf(f1.x, w, acc[2]);
    acc[3] = fmaf(f1.y, w, acc[3]);
}

template <int TPN, bool RELU>
__global__ void k_agg_h(const uint2* __restrict__ Hh,
                        const float* __restrict__ bias,
                        float4* __restrict__ out, int n) {
    int t = blockIdx.x * blockDim.x + threadIdx.x;
    int node = t / TPN;
    int q = t % TPN;
    if (node >= n) return;

    float dv = g_dinv[node];
    int beg = __ldg(&g_rowptr[node]);
    int end = __ldg(&g_rowptr[node + 1]);

    float acc[4] = {};
    uint2 hv = __ldg(&Hh[(size_t)node * TPN + q]);
    h4_fma(acc, hv, dv * dv);

    if (beg < end) {
        int2 cur = __ldg(&g_csr[beg]);
        for (int e = beg; e < end; e++) {
            int2 nxt = (e + 1 < end) ? __ldg(&g_csr[e + 1]) : cur;
            float w = __int_as_float(cur.y) * dv;
            uint2 v = __ldg(&Hh[(size_t)cur.x * TPN + q]);
            h4_fma(acc, v, w);
            cur = nxt;
        }
    }
    float4 bb = *reinterpret_cast<const float4*>(&bias[q * 4]);
    float4 o = make_float4(acc[0] + bb.x, acc[1] + bb.y,
                           acc[2] + bb.z, acc[3] + bb.w);
    if (RELU) {
        o.x = fmaxf(o.x, 0.f); o.y = fmaxf(o.y, 0.f);
        o.z = fmaxf(o.z, 0.f); o.w = fmaxf(o.w, 0.f);
    }
    out[(size_t)node * TPN + q] = o;
}

// ---------------------------------------------------------------------------
// launch
// ---------------------------------------------------------------------------
extern "C" void kernel_launch(void* const* d_in, const int* in_sizes, int n_in,
                              void* d_out, int out_size) {
    const float* x   = (const float*)d_in[0];
    const int*   ei  = (const int*)d_in[1];    // int32 (JAX x64 disabled)
    const float* W1  = (const float*)d_in[2];
    const float* b1  = (const float*)d_in[3];
    const float* W2  = (const float*)d_in[4];
    const float* b2  = (const float*)d_in[5];
    float*       out = (float*)d_out;

    const int n = in_sizes[0] / D_IN;       // 50000
    const int E = in_sizes[1] / 2;          // 800000
    const int* srcs = ei;
    const int* dsts = ei + E;

    float* H1 = nullptr; __half* H1h = nullptr;
    float* OUT1 = nullptr; float* H2 = nullptr; __half* H2h = nullptr;
    cudaGetSymbolAddress((void**)&H1,   g_H1);
    cudaGetSymbolAddress((void**)&H1h,  g_H1h);
    cudaGetSymbolAddress((void**)&OUT1, g_OUT1);
    cudaGetSymbolAddress((void**)&H2,   g_H2);
    cudaGetSymbolAddress((void**)&H2h,  g_H2h);

    static cudaStream_t s1 = nullptr;
    static cudaEvent_t  evFork = nullptr, evJoin = nullptr;
    if (!s1) {
        cudaFuncSetAttribute(k_gemm_tc,
                             cudaFuncAttributeMaxDynamicSharedMemorySize, GEMM_SMEM);
        cudaStreamCreateWithFlags(&s1, cudaStreamNonBlocking);
        cudaEventCreateWithFlags(&evFork, cudaEventDisableTiming);
        cudaEventCreateWithFlags(&evJoin, cudaEventDisableTiming);
    }

    const int T = 256;
    const int mblocks = (n + 127) / 128;    // 391

    // ---- fork: GEMM1 + fp16 convert on s1, concurrent with CSR build ----
    cudaEventRecord(evFork, 0);
    cudaStreamWaitEvent(s1, evFork, 0);
    {
        dim3 grid(D_HID / 64, mblocks);
        k_gemm_tc<<<grid, 256, GEMM_SMEM, s1>>>(x, W1, H1, n, D_IN, D_HID);
    }
    {
        int total4 = M_PAD * D_HID / 4;     // 1.6M
        k_convert_h<<<(total4 + T - 1) / T, T, 0, s1>>>(
            (const float4*)H1, (uint2*)H1h, total4);
    }
    cudaEventRecord(evJoin, s1);

    // ---- CSR build on capture stream (3 nodes) ----
    k_deg_hist<<<(E + T - 1) / T, T>>>(dsts, E);
    k_scan_fused<<<NBLK, T>>>(n, E);
    k_bin<<<(E + T - 1) / T, T>>>(srcs, dsts, E);

    // ---- join ----
    cudaStreamWaitEvent(0, evJoin, 0);

    // agg1 (fp16 gather, TPN=32): OUT1 = relu(agg(H1h) + b1)
    {
        long long work = (long long)n * 32;
        k_agg_h<32, true><<<(int)((work + T - 1) / T), T>>>(
            (const uint2*)H1h, b1, (float4*)OUT1, n);
    }

    // GEMM2: H2 = OUT1 @ W2 (fp32 out)
    {
        dim3 grid(D_OUT / 64, mblocks);
        k_gemm_tc<<<grid, 256, GEMM_SMEM>>>(OUT1, W2, H2, n, D_HID, D_OUT);
    }

    // convert H2 -> fp16 mirror
    {
        int total4 = M_PAD * D_OUT / 4;     // 800K
        k_convert_h<<<(total4 + T - 1) / T, T>>>(
            (const float4*)H2, (uint2*)H2h, total4);
    }

    // agg2 (fp16 gather, TPN=16): out = agg(H2h) + b2
    {
        long long work = (long long)n * 16;
        k_agg_h<16, false><<<(int)((work + T - 1) / T), T>>>(
            (const uint2*)H2h, b2, (float4*)out, n);
    }
}